// round 12
// baseline (speedup 1.0000x reference)
#include <cuda_runtime.h>

#define NB 4
#define NP 4096
#define TP (NB*NP)
#define KN 40
#define NE (TP*KN)
#define SLP 0.2f
#define FULLM 0xffffffffu

// ----------------------------- scratch -----------------------------
__device__ unsigned g_DK[(size_t)NB*NP*NP];   // encoded distance keys
__device__ int      g_idx[NE];
__device__ float    g_uv[TP*128];             // [u(64) | v(64)] per point
__device__ float    g_xc[TP*192];
__device__ float    g_sq[TP];
__device__ unsigned g_gm[NB*1024];
__device__ float    g_c1[NB*256];
__device__ float    g_h1[(size_t)TP*256];
__device__ float    g_h2[(size_t)TP*256];
__device__ float    g_h3[(size_t)TP*128];
__device__ float    g_wad3[128*64], g_bv3[128];
__device__ float    g_wad5[128*64], g_bv5[128];
__device__ float    g_wt[1088*256];

__device__ __forceinline__ float lrelu_f(float x){ return fmaxf(x, SLP*x); }
__device__ __forceinline__ unsigned fenc(float f){
    unsigned u = __float_as_uint(f);
    return u ^ (unsigned)(((int)u >> 31) | 0x80000000);
}
__device__ __forceinline__ float fdec(unsigned e){
    return __uint_as_float((e & 0x80000000u) ? (e & 0x7FFFFFFFu) : ~e);
}

// ------------- symmetric distance GEMM -> encoded keys, upper-triangle blocks ------------
__global__ void __launch_bounds__(256,2) dist_gemm_sym(const float* __restrict__ X, int lda,
                                                       unsigned* __restrict__ Dm)
{
    __shared__ __align__(16) float As[16][128];
    __shared__ __align__(16) float Bs[16][128];
    __shared__ unsigned T[32][129];
    const int tid = threadIdx.x, z = blockIdx.z;
    const int t = blockIdx.x;
    int bj = (int)((sqrtf(8.f*(float)t + 1.f) - 1.f) * 0.5f);
    while ((bj+1)*(bj+2)/2 <= t) bj++;
    while (bj*(bj+1)/2 > t) bj--;
    const int bi = t - bj*(bj+1)/2;                 // bi <= bj
    const int m0 = bi<<7, n0 = bj<<7;
    const float* Xb = X + (size_t)z*NP*lda;
    const int lr = tid>>1, lc = (tid&1)<<3;
    const float* Arow = Xb + (size_t)(m0+lr)*lda + lc;
    const float* Brow = Xb + (size_t)(n0+lr)*lda + lc;
    const int tx = tid&15, ty = tid>>4;
    float acc[8][8] = {};
    for (int kc=0; kc<64; kc+=16){
        float4 a0 = *(const float4*)(Arow+kc);
        float4 a1 = *(const float4*)(Arow+kc+4);
        float4 b0 = *(const float4*)(Brow+kc);
        float4 b1 = *(const float4*)(Brow+kc+4);
        As[lc+0][lr]=a0.x; As[lc+1][lr]=a0.y; As[lc+2][lr]=a0.z; As[lc+3][lr]=a0.w;
        As[lc+4][lr]=a1.x; As[lc+5][lr]=a1.y; As[lc+6][lr]=a1.z; As[lc+7][lr]=a1.w;
        Bs[lc+0][lr]=b0.x; Bs[lc+1][lr]=b0.y; Bs[lc+2][lr]=b0.z; Bs[lc+3][lr]=b0.w;
        Bs[lc+4][lr]=b1.x; Bs[lc+5][lr]=b1.y; Bs[lc+6][lr]=b1.z; Bs[lc+7][lr]=b1.w;
        __syncthreads();
        #pragma unroll
        for (int kk=0; kk<16; kk++){
            float4 x0 = *(const float4*)&As[kk][ty<<3];
            float4 x1 = *(const float4*)&As[kk][(ty<<3)+4];
            float4 y0 = *(const float4*)&Bs[kk][tx<<3];
            float4 y1 = *(const float4*)&Bs[kk][(tx<<3)+4];
            float ar[8]={x0.x,x0.y,x0.z,x0.w,x1.x,x1.y,x1.z,x1.w};
            float br[8]={y0.x,y0.y,y0.z,y0.w,y1.x,y1.y,y1.z,y1.w};
            #pragma unroll
            for (int i=0;i<8;i++)
                #pragma unroll
                for (int j=0;j<8;j++) acc[i][j] = fmaf(ar[i], br[j], acc[i][j]);
        }
        __syncthreads();
    }
    const float* sqb = g_sq + z*NP;
    unsigned* Db = Dm + (size_t)z*NP*NP;
    float sc[8];
    #pragma unroll
    for (int j=0;j<8;j++) sc[j] = sqb[n0 + (tx<<3) + j];
    #pragma unroll
    for (int i=0;i<8;i++){
        int r = m0 + (ty<<3) + i;
        float sr = sqb[r];
        uint4 v0, v1;
        v0.x=fenc(2.f*acc[i][0]-sr-sc[0]); v0.y=fenc(2.f*acc[i][1]-sr-sc[1]);
        v0.z=fenc(2.f*acc[i][2]-sr-sc[2]); v0.w=fenc(2.f*acc[i][3]-sr-sc[3]);
        v1.x=fenc(2.f*acc[i][4]-sr-sc[4]); v1.y=fenc(2.f*acc[i][5]-sr-sc[5]);
        v1.z=fenc(2.f*acc[i][6]-sr-sc[6]); v1.w=fenc(2.f*acc[i][7]-sr-sc[7]);
        *(uint4*)&Db[(size_t)r*NP + n0 + (tx<<3)]     = v0;
        *(uint4*)&Db[(size_t)r*NP + n0 + (tx<<3) + 4] = v1;
    }
    if (bi == bj) return;
    const int r_m = tid>>1, h = tid&1;
    for (int c=0; c<4; c++){
        __syncthreads();
        if ((ty>>2) == c){
            int rloc = (ty&3)<<3;
            #pragma unroll
            for (int i=0;i<8;i++){
                float sri = sqb[m0 + (ty<<3) + i];
                #pragma unroll
                for (int j=0;j<8;j++)
                    T[rloc+i][(tx<<3)+j] = fenc(2.f*acc[i][j]-sri-sc[j]);
            }
        }
        __syncthreads();
        unsigned* dst = &Db[(size_t)(n0+r_m)*NP + m0 + (c<<5) + (h<<4)];
        uint4 w0, w1, w2, w3;
        int rb = h<<4;
        w0.x=T[rb+ 0][r_m]; w0.y=T[rb+ 1][r_m]; w0.z=T[rb+ 2][r_m]; w0.w=T[rb+ 3][r_m];
        w1.x=T[rb+ 4][r_m]; w1.y=T[rb+ 5][r_m]; w1.z=T[rb+ 6][r_m]; w1.w=T[rb+ 7][r_m];
        w2.x=T[rb+ 8][r_m]; w2.y=T[rb+ 9][r_m]; w2.z=T[rb+10][r_m]; w2.w=T[rb+11][r_m];
        w3.x=T[rb+12][r_m]; w3.y=T[rb+13][r_m]; w3.z=T[rb+14][r_m]; w3.w=T[rb+15][r_m];
        ((uint4*)dst)[0]=w0; ((uint4*)dst)[1]=w1; ((uint4*)dst)[2]=w2; ((uint4*)dst)[3]=w3;
    }
}

// ------------------- generic 128x64 GEMM: C = epi(A * B^T) -------------------------------
template<int MODE>
__global__ void __launch_bounds__(256,2) gemm128(
    const float* __restrict__ A, int lda, const float* __restrict__ B, int ldb,
    float* __restrict__ C, int ldc, int K,
    const float* __restrict__ bias, unsigned* __restrict__ gmax, int ncols)
{
    __shared__ __align__(16) float As[16][128];
    __shared__ __align__(16) float Bs[16][64];
    __shared__ unsigned gred[64];
    const int tid = threadIdx.x;
    const int m0 = blockIdx.y*128, n0 = blockIdx.x*64;
    const int lrA = tid>>1, lcA = (tid&1)<<3;
    const int lrB = tid>>2, lcB = (tid&3)<<2;
    const float* Arow = A + (size_t)(m0+lrA)*lda + lcA;
    const float* Brow = B + (size_t)(n0+lrB)*ldb + lcB;
    const int tx = tid&15, ty = tid>>4;
    float acc[8][4] = {};
    for (int kc=0; kc<K; kc+=16){
        float4 a0 = *(const float4*)(Arow+kc);
        float4 a1 = *(const float4*)(Arow+kc+4);
        float4 b4 = *(const float4*)(Brow+kc);
        As[lcA+0][lrA]=a0.x; As[lcA+1][lrA]=a0.y; As[lcA+2][lrA]=a0.z; As[lcA+3][lrA]=a0.w;
        As[lcA+4][lrA]=a1.x; As[lcA+5][lrA]=a1.y; As[lcA+6][lrA]=a1.z; As[lcA+7][lrA]=a1.w;
        Bs[lcB+0][lrB]=b4.x; Bs[lcB+1][lrB]=b4.y; Bs[lcB+2][lrB]=b4.z; Bs[lcB+3][lrB]=b4.w;
        __syncthreads();
        #pragma unroll
        for (int kk=0; kk<16; kk++){
            float4 x0 = *(const float4*)&As[kk][ty<<3];
            float4 x1 = *(const float4*)&As[kk][(ty<<3)+4];
            float4 y0 = *(const float4*)&Bs[kk][tx<<2];
            float ar[8]={x0.x,x0.y,x0.z,x0.w,x1.x,x1.y,x1.z,x1.w};
            float br[4]={y0.x,y0.y,y0.z,y0.w};
            #pragma unroll
            for (int i=0;i<8;i++)
                #pragma unroll
                for (int j=0;j<4;j++) acc[i][j] = fmaf(ar[i], br[j], acc[i][j]);
        }
        __syncthreads();
    }
    if (MODE==5){
        if (tid<64) gred[tid]=0u;
        __syncthreads();
        #pragma unroll
        for (int j=0;j<4;j++){
            int c = (tx<<2)+j;
            float bb = bias[n0+c];
            float m = -3.4e38f;
            #pragma unroll
            for (int i=0;i<8;i++) m = fmaxf(m, lrelu_f(acc[i][j]+bb));
            atomicMax(&gred[c], fenc(m));
        }
        __syncthreads();
        if (tid<64){
            int bb = m0 >> 12;
            atomicMax(&gmax[bb*ncols + n0 + tid], gred[tid]);
        }
        return;
    }
    #pragma unroll
    for (int i=0;i<8;i++){
        int r = m0 + (ty<<3) + i;
        float4 v;
        #pragma unroll
        for (int j=0;j<4;j++){
            int c = n0 + (tx<<2) + j;
            float val = acc[i][j];
            if (MODE==1 || MODE==2) val += bias[c];
            if (MODE==3)            val += bias[(m0>>12)*ncols + c];
            if (MODE==2 || MODE==3) val = lrelu_f(val);
            ((float*)&v)[j] = val;
        }
        *(float4*)&C[(size_t)r*ldc + n0 + (tx<<2)] = v;
    }
}

// ------------------- fused edge GEMM + per-point max (global REDG) -----------------------
__global__ void __launch_bounds__(256,2) edge_gemm(
    const float* __restrict__ UV,
    const int* __restrict__ IDX, const float* __restrict__ W,
    const float* __restrict__ bias, unsigned* __restrict__ Xout, int ldx)
{
    __shared__ __align__(16) float As[16][128];
    __shared__ __align__(16) float Bs[16][64];
    const int tid = threadIdx.x;
    const int m0 = blockIdx.x*128;
    const int lr = tid>>1, lc = (tid&1)<<3;
    const int e  = m0 + lr;
    const int p  = e / KN;
    const int jg = IDX[e];
    const float* urow = UV + (size_t)jg*128 + lc;
    const float* vrow = UV + (size_t)p *128 + 64 + lc;
    const int lrB = tid>>2, lcB = (tid&3)<<2;
    const float* wrow = W + lrB*64 + lcB;
    const int tx = tid&15, ty = tid>>4;
    float acc[8][4] = {};
    #pragma unroll
    for (int kc=0; kc<64; kc+=16){
        float4 u0=*(const float4*)(urow+kc), u1=*(const float4*)(urow+kc+4);
        float4 v0=*(const float4*)(vrow+kc), v1=*(const float4*)(vrow+kc+4);
        float4 w4=*(const float4*)(wrow+kc);
        As[lc+0][lr]=lrelu_f(u0.x+v0.x); As[lc+1][lr]=lrelu_f(u0.y+v0.y);
        As[lc+2][lr]=lrelu_f(u0.z+v0.z); As[lc+3][lr]=lrelu_f(u0.w+v0.w);
        As[lc+4][lr]=lrelu_f(u1.x+v1.x); As[lc+5][lr]=lrelu_f(u1.y+v1.y);
        As[lc+6][lr]=lrelu_f(u1.z+v1.z); As[lc+7][lr]=lrelu_f(u1.w+v1.w);
        Bs[lcB+0][lrB]=w4.x; Bs[lcB+1][lrB]=w4.y; Bs[lcB+2][lrB]=w4.z; Bs[lcB+3][lrB]=w4.w;
        __syncthreads();
        #pragma unroll
        for (int kk=0; kk<16; kk++){
            float4 x0 = *(const float4*)&As[kk][ty<<3];
            float4 x1 = *(const float4*)&As[kk][(ty<<3)+4];
            float4 y0 = *(const float4*)&Bs[kk][tx<<2];
            float ar[8]={x0.x,x0.y,x0.z,x0.w,x1.x,x1.y,x1.z,x1.w};
            float br[4]={y0.x,y0.y,y0.z,y0.w};
            #pragma unroll
            for (int i=0;i<8;i++)
                #pragma unroll
                for (int j=0;j<4;j++) acc[i][j] = fmaf(ar[i], br[j], acc[i][j]);
        }
        __syncthreads();
    }
    const int e0 = m0 + (ty<<3);
    const int p0 = e0 / KN;
    const int p7 = (e0+7) / KN;
    const int s  = (p7 != p0) ? (p7*KN - e0) : 8;
    #pragma unroll
    for (int j=0;j<4;j++){
        int c = (tx<<2)+j;
        float bb = bias[c];
        float mA = -3.4e38f, mB = -3.4e38f;
        #pragma unroll
        for (int i=0;i<8;i++){
            float v = lrelu_f(acc[i][j]+bb);
            if (i < s) mA = fmaxf(mA, v); else mB = fmaxf(mB, v);
        }
        atomicMax(&Xout[(size_t)p0*ldx + c], fenc(mA));
        if (p7 != p0) atomicMax(&Xout[(size_t)p7*ldx + c], fenc(mB));
    }
}

// =================== top-40: 11-bit first radix + rank-count finish ======================
// Shared machinery is expressed per-variant (GEO: keys in smem; DK: keys in L2).

// 2048-bin suffix-scan digit select. Returns via s_dsel/s_rem.
__device__ __forceinline__ void select2048(int* hist, int* warptot,
                                           int& s_dsel_ref, int& s_rem_ref,
                                           int lane, int wrp, int tid, int r)
{
    int v[8], tot=0;
    #pragma unroll
    for (int i=0;i<8;i++){ v[i]=hist[(tid<<3)+i]; tot+=v[i]; }
    int s=tot;
    #pragma unroll
    for (int d=1; d<32; d<<=1){
        int t2 = __shfl_down_sync(FULLM, s, d);
        if (lane + d < 32) s += t2;
    }
    if (lane == 0) warptot[wrp] = s;
    __syncthreads();
    int offs=0;
    #pragma unroll
    for (int w=0; w<8; w++) if (w > wrp) offs += warptot[w];
    int Sgt = s + offs - tot;     // keys with bin > tid*8+7
    int suf = 0;
    #pragma unroll
    for (int i=7; i>=0; i--){
        suf += v[i];
        int c = Sgt + suf;        // keys with bin >= tid*8+i
        if (c >= r && c - v[i] < r){ s_dsel_ref = (tid<<3)+i; s_rem_ref = r - (c - v[i]); }
    }
}

// 256-bin suffix-scan digit select (refinement).
__device__ __forceinline__ void select256(int* hist, int* warptot,
                                          int& s_dsel_ref, int& s_rem_ref,
                                          int lane, int wrp, int tid, int r)
{
    int val = hist[tid];
    int s = val;
    #pragma unroll
    for (int d=1; d<32; d<<=1){
        int t2 = __shfl_down_sync(FULLM, s, d);
        if (lane + d < 32) s += t2;
    }
    if (lane == 0) warptot[wrp] = s;
    __syncthreads();
    int offs=0;
    #pragma unroll
    for (int w=0; w<8; w++) if (w > wrp) offs += warptot[w];
    int S = s + offs;
    if (S >= r && S - val < r){ s_dsel_ref = tid; s_rem_ref = r - (S - val); }
}

#define TOPK_SHARED \
    __shared__ int hist[2048]; \
    __shared__ unsigned short cbuf[NP]; \
    __shared__ int warptot[8]; \
    __shared__ int s_dsel, s_rem, s_cout, s_cnt;

#define TOPK_BODY(KEY_EXPR_I, KEY_EXPR_GI) \
    /* ---- pass B: emit bin>T, compact bin==T ---- */ \
    { \
        const int T = s_dsel; \
        for (int it=0; it<16; it++){ \
            int i = it*256 + tid; \
            unsigned kx = (KEY_EXPR_I); \
            int bin = kx >> 21; \
            bool gt = bin > T, eq = bin == T; \
            unsigned bg = __ballot_sync(FULLM, gt); \
            unsigned be = __ballot_sync(FULLM, eq); \
            int baseg=0, basee=0; \
            if (lane==0){ \
                if (bg) baseg = atomicAdd(&s_cout, __popc(bg)); \
                if (be) basee = atomicAdd(&s_cnt,  __popc(be)); \
            } \
            baseg = __shfl_sync(FULLM, baseg, 0); \
            basee = __shfl_sync(FULLM, basee, 0); \
            unsigned ltm = (1u<<lane)-1u; \
            if (gt) OUT[row*KN + baseg + __popc(bg&ltm)] = base + i; \
            if (eq) cbuf[basee + __popc(be&ltm)] = (unsigned short)i; \
        } \
        __syncthreads(); \
    } \
    int C = s_cnt; \
    /* ---- rare refinement passes on remaining 21 bits ---- */ \
    { \
        const int shf[3] = {13,5,0}; \
        const unsigned msk[3] = {255u,255u,31u}; \
        int pi = 0; \
        while (C > 128 && pi < 3){ \
            const int sh = shf[pi]; const unsigned mk = msk[pi]; \
            if (tid < 256) hist[tid] = 0; \
            int r_cur = s_rem; \
            __syncthreads(); \
            const int nt = (C + 255) >> 8; \
            for (int it=0; it<nt; it++){ \
                int ii = it*256 + tid; \
                if (ii < C){ \
                    int gi = cbuf[ii]; \
                    unsigned kx = (KEY_EXPR_GI); \
                    atomicAdd(&hist[(kx>>sh)&mk], 1); \
                } \
            } \
            __syncthreads(); \
            select256(hist, warptot, s_dsel, s_rem, lane, wrp, tid, r_cur); \
            if (tid == 0) s_cnt = 0; \
            __syncthreads(); \
            const int ds = s_dsel; \
            for (int it=0; it<nt; it++){ \
                int ii = it*256 + tid; \
                bool vld = ii < C; \
                int gi = 0; unsigned kx = 0; \
                if (vld){ gi = cbuf[ii]; kx = (KEY_EXPR_GI); } \
                __syncthreads(); \
                int dig = vld ? (int)((kx>>sh)&mk) : 0x1FF; \
                bool gt = vld && dig > ds; \
                bool eq = vld && dig == ds; \
                unsigned bg = __ballot_sync(FULLM, gt); \
                unsigned be = __ballot_sync(FULLM, eq); \
                int baseg=0, basee=0; \
                if (lane==0){ \
                    if (bg) baseg = atomicAdd(&s_cout, __popc(bg)); \
                    if (be) basee = atomicAdd(&s_cnt,  __popc(be)); \
                } \
                baseg = __shfl_sync(FULLM, baseg, 0); \
                basee = __shfl_sync(FULLM, basee, 0); \
                unsigned ltm = (1u<<lane)-1u; \
                if (gt) OUT[row*KN + baseg + __popc(bg&ltm)] = base + gi; \
                if (eq) cbuf[basee + __popc(be&ltm)] = (unsigned short)gi; \
            } \
            __syncthreads(); \
            C = s_cnt; \
            pi++; \
        } \
    }

// ---------------- GEO variant: keys computed from 3-D geometry, held in smem -------------
__global__ void __launch_bounds__(256) topk40_geo(
    const float* __restrict__ P3, const float* __restrict__ sqv, int* __restrict__ OUT)
{
    __shared__ unsigned keys[NP];
    TOPK_SHARED
    const int row = blockIdx.x, tid = threadIdx.x;
    const int lane = tid & 31, wrp = tid >> 5;
    const int base = (row >> 12) << 12;
    #pragma unroll
    for (int i=0;i<8;i++) hist[tid + (i<<8)] = 0;
    if (tid == 0){ s_cout = 0; s_cnt = 0; }
    __syncthreads();
    // pass A: keygen + 11-bit histogram
    {
        const float x0=P3[(size_t)row*3], x1=P3[(size_t)row*3+1], x2=P3[(size_t)row*3+2];
        const float sn = sqv[row];
        for (int i = tid; i < NP; i += 256){
            const float* pm = P3 + (size_t)(base+i)*3;
            float d = 2.f*(x0*pm[0]+x1*pm[1]+x2*pm[2]) - sn - sqv[base+i];
            unsigned kx = fenc(d);
            keys[i] = kx;
            atomicAdd(&hist[kx>>21], 1);
        }
    }
    __syncthreads();
    select2048(hist, warptot, s_dsel, s_rem, lane, wrp, tid, KN);
    __syncthreads();
    TOPK_BODY(keys[i], keys[gi])
    // ---- rank-by-count finish (exact, stable smallest-index ties) ----
    const int rem = s_rem;
    for (int t = tid; t < C; t += 256){
        int gi = cbuf[t];
        unsigned kx = keys[gi];
        int nb = 0;
        for (int q=0; q<C; q++){
            int gq = cbuf[q];
            unsigned kq = keys[gq];
            nb += (kq > kx) || (kq == kx && gq < gi);
        }
        if (nb < rem) OUT[row*KN + atomicAdd(&s_cout,1)] = base + gi;
    }
}

// ---------------- DK variant: keys pre-encoded in global (L2) ----------------------------
__global__ void __launch_bounds__(256) topk40_dk(
    const unsigned* __restrict__ DK, int* __restrict__ OUT)
{
    TOPK_SHARED
    const int row = blockIdx.x, tid = threadIdx.x;
    const int lane = tid & 31, wrp = tid >> 5;
    const int base = (row >> 12) << 12;
    const unsigned* drow = DK + (size_t)row*NP;
    #pragma unroll
    for (int i=0;i<8;i++) hist[tid + (i<<8)] = 0;
    if (tid == 0){ s_cout = 0; s_cnt = 0; }
    __syncthreads();
    // pass A: 11-bit histogram straight from L2
    for (int i = tid; i < NP; i += 256){
        unsigned kx = __ldg(&drow[i]);
        atomicAdd(&hist[kx>>21], 1);
    }
    __syncthreads();
    select2048(hist, warptot, s_dsel, s_rem, lane, wrp, tid, KN);
    __syncthreads();
    TOPK_BODY(__ldg(&drow[i]), __ldg(&drow[gi]))
    // ---- rank-by-count finish; stage candidate keys into hist space when they fit ----
    const int rem = s_rem;
    const bool staged = (C <= 2048);
    if (staged){
        for (int t = tid; t < C; t += 256) hist[t] = (int)__ldg(&drow[cbuf[t]]);
    }
    __syncthreads();
    for (int t = tid; t < C; t += 256){
        int gi = cbuf[t];
        unsigned kx = staged ? (unsigned)hist[t] : __ldg(&drow[gi]);
        int nb = 0;
        for (int q=0; q<C; q++){
            int gq = cbuf[q];
            unsigned kq = staged ? (unsigned)hist[q] : __ldg(&drow[gq]);
            nb += (kq > kx) || (kq == kx && gq < gi);
        }
        if (nb < rem) OUT[row*KN + atomicAdd(&s_cout,1)] = base + gi;
    }
}

// ----------------------------- small kernels ---------------------------------------------
__global__ void sqnormk(const float* __restrict__ X, int ld, int C){
    int p = blockIdx.x*256 + threadIdx.x;
    if (p>=TP) return;
    const float* r = X + (size_t)p*ld;
    float s=0.f;
    for (int c=0;c<C;c++) s = fmaf(r[c],r[c],s);
    g_sq[p]=s;
}
__global__ void uv1k(const float* __restrict__ P, const float* __restrict__ W1, const float* __restrict__ b1){
    int g = blockIdx.x*256 + threadIdx.x;
    int o = g&63, p = g>>6;
    const float* x = P + (size_t)p*3;
    float u=0.f, v=b1[o];
    #pragma unroll
    for (int c=0;c<3;c++){
        float wa=W1[o*6+c], wb=W1[o*6+3+c];
        u = fmaf(wa, x[c], u);
        v = fmaf(wb-wa, x[c], v);
    }
    g_uv[(size_t)p*128 + o]      = u;
    g_uv[(size_t)p*128 + 64 + o] = v;
}
__global__ void wprep2k(const float* __restrict__ W, const float* __restrict__ b,
                        float* __restrict__ wad, float* __restrict__ bv){
    int g = blockIdx.x*256 + threadIdx.x;
    if (g < 8192){
        int o = g>>6, c = g&63;
        float val;
        if (o < 64) val = W[o*128 + c];
        else        val = W[(o-64)*128 + 64 + c] - W[(o-64)*128 + c];
        wad[g] = val;
    }
    if (g < 128) bv[g] = (g < 64) ? 0.f : b[g-64];
}
__global__ void initenck(int off){
    int g = blockIdx.x*256 + threadIdx.x;
    int p=g>>6, c=g&63;
    ((unsigned*)g_xc)[(size_t)p*192 + off + c]=0u;
}
__global__ void decenck(int off){
    int g = blockIdx.x*256 + threadIdx.x;
    int p=g>>6, c=g&63;
    size_t ix=(size_t)p*192 + off + c;
    unsigned e = ((unsigned*)g_xc)[ix];
    g_xc[ix]=fdec(e);
}
__global__ void initgk(){ int g=blockIdx.x*256+threadIdx.x; if (g<NB*1024) g_gm[g]=0u; }
__global__ void maxedgek(){
    int p = blockIdx.x, o = threadIdx.x;
    float v = g_uv[(size_t)p*128 + 64 + o];
    float best = -3.4e38f;
    #pragma unroll 4
    for (int j=0;j<KN;j++){
        int jg = g_idx[p*KN+j];
        best = fmaxf(best, lrelu_f(g_uv[(size_t)jg*128 + o] + v));
    }
    g_xc[(size_t)p*192 + 128 + o] = best;
}
__global__ void wp1tk(const float* __restrict__ Wp1){
    int g = blockIdx.x*256 + threadIdx.x;
    if (g >= 1088*256) return;
    int o = g&255, j = g>>8;
    g_wt[(size_t)j*256 + o] = Wp1[(size_t)o*1280 + 192 + j];
}
__global__ void __launch_bounds__(256) globk(
    const float* __restrict__ label, const float* __restrict__ W7,
    const float* __restrict__ b7, const float* __restrict__ bp1)
{
    __shared__ float gl[1088];
    int b = blockIdx.x, tid = threadIdx.x;
    for (int i=tid;i<1024;i+=256) gl[i]=fdec(g_gm[b*1024+i]);
    if (tid<64){
        float a=b7[tid];
        #pragma unroll
        for (int c=0;c<16;c++) a = fmaf(label[b*16+c], W7[tid*16+c], a);
        gl[1024+tid]=lrelu_f(a);
    }
    __syncthreads();
    float a = bp1[tid];
    #pragma unroll 8
    for (int j=0;j<1088;j++) a = fmaf(g_wt[(size_t)j*256 + tid], gl[j], a);
    g_c1[b*256+tid]=a;
}
__global__ void outk(const float* __restrict__ Wp4, float* __restrict__ out){
    int g = blockIdx.x*256 + threadIdx.x;
    int s = g%6, p = g/6;
    const float* h = g_h3 + (size_t)p*128;
    const float* w = Wp4 + s*128;
    float a=0.f;
    #pragma unroll 8
    for (int c=0;c<128;c++) a = fmaf(h[c], w[c], a);
    out[g]=a;
}

// ----------------------------- host ------------------------------------------------------
static void* symaddr(const void* s){ void* p=nullptr; cudaGetSymbolAddress(&p, s); return p; }

extern "C" void kernel_launch(void* const* d_in, const int* in_sizes, int n_in,
                              void* d_out, int out_size)
{
    const float* points=(const float*)d_in[0];
    const float* label =(const float*)d_in[1];
    const float *W1=(const float*)d_in[2],  *b1=(const float*)d_in[3];
    const float *W2=(const float*)d_in[4],  *b2=(const float*)d_in[5];
    const float *W3=(const float*)d_in[6],  *b3=(const float*)d_in[7];
    const float *W4=(const float*)d_in[8],  *b4=(const float*)d_in[9];
    const float *W5=(const float*)d_in[10], *b5=(const float*)d_in[11];
    const float *W6=(const float*)d_in[12], *b6=(const float*)d_in[13];
    const float *W7=(const float*)d_in[14], *b7=(const float*)d_in[15];
    const float *Wp1=(const float*)d_in[16],*bp1=(const float*)d_in[17];
    const float *Wp2=(const float*)d_in[18],*bp2=(const float*)d_in[19];
    const float *Wp3=(const float*)d_in[20],*bp3=(const float*)d_in[21];
    const float *Wp4=(const float*)d_in[22];
    float* out=(float*)d_out;

    unsigned* pDK =(unsigned*)symaddr(g_DK);
    int*      pIdx=(int*)     symaddr(g_idx);
    float*    pUV =(float*)   symaddr(g_uv);
    float*    pXc =(float*)   symaddr(g_xc);
    float*    pSq =(float*)   symaddr(g_sq);
    unsigned* pGm =(unsigned*)symaddr(g_gm);
    float*    pC1 =(float*)   symaddr(g_c1);
    float*    pH1 =(float*)   symaddr(g_h1);
    float*    pH2 =(float*)   symaddr(g_h2);
    float*    pH3 =(float*)   symaddr(g_h3);
    float*    pWad3=(float*)  symaddr(g_wad3);
    float*    pBv3 =(float*)  symaddr(g_bv3);
    float*    pWad5=(float*)  symaddr(g_wad5);
    float*    pBv5 =(float*)  symaddr(g_bv5);

    // launches 1-3 prep; launch 4 = topk40_geo for ncu
    sqnormk<<<64,256>>>(points,3,3);
    wprep2k<<<32,256>>>(W3,b3,pWad3,pBv3);
    wprep2k<<<32,256>>>(W5,b5,pWad5,pBv5);
    topk40_geo<<<TP,256>>>(points, pSq, pIdx);
    wp1tk<<<1088,256>>>(Wp1);
    initgk<<<16,256>>>();

    // ---------- EdgeConv block 1 ----------
    uv1k<<<4096,256>>>(points,W1,b1);
    initenck<<<4096,256>>>(0);
    edge_gemm<<<NE/128,256>>>(pUV,pIdx,W2,b2,(unsigned*)pXc+0,192);
    decenck<<<4096,256>>>(0);

    // ---------- EdgeConv block 2 ----------
    sqnormk<<<64,256>>>(pXc+0,192,64);
    dist_gemm_sym<<<dim3(528,1,NB),256>>>(pXc+0,192,pDK);
    topk40_dk<<<TP,256>>>(pDK, pIdx);
    gemm128<1><<<dim3(2,128),256>>>(pXc+0,192, pWad3,64, pUV,128, 64, pBv3,nullptr,0);
    initenck<<<4096,256>>>(64);
    edge_gemm<<<NE/128,256>>>(pUV,pIdx,W4,b4,(unsigned*)pXc+64,192);
    decenck<<<4096,256>>>(64);

    // ---------- EdgeConv block 3 (single layer -> gather/max) ----------
    sqnormk<<<64,256>>>(pXc+64,192,64);
    dist_gemm_sym<<<dim3(528,1,NB),256>>>(pXc+64,192,pDK);
    topk40_dk<<<TP,256>>>(pDK, pIdx);
    gemm128<1><<<dim3(2,128),256>>>(pXc+64,192, pWad5,64, pUV,128, 64, pBv5,nullptr,0);
    maxedgek<<<TP,64>>>();

    // ---------- global feature ----------
    gemm128<5><<<dim3(16,128),256>>>(pXc,192, W6,192, nullptr,0, 192, b6,pGm,1024);
    globk<<<NB,256>>>(label,W7,b7,bp1);

    // ---------- segmentation head ----------
    gemm128<3><<<dim3(4,128),256>>>(pXc,192, Wp1,1280, pH1,256, 192, pC1,nullptr,256);
    gemm128<2><<<dim3(4,128),256>>>(pH1,256, Wp2,256,  pH2,256, 256, bp2,nullptr,0);
    gemm128<2><<<dim3(2,128),256>>>(pH2,256, Wp3,256,  pH3,128, 256, bp3,nullptr,0);
    outk<<<384,256>>>(Wp4,out);
}

// round 15
// speedup vs baseline: 1.3604x; 1.3604x over previous
#include <cuda_runtime.h>

#define NB 4
#define NP 4096
#define TP (NB*NP)
#define KN 40
#define NE (TP*KN)
#define SLP 0.2f
#define FULLM 0xffffffffu

// ----------------------------- scratch -----------------------------
__device__ unsigned g_DK[(size_t)NB*NP*NP];   // encoded distance keys
__device__ int      g_idx[NE];
__device__ float    g_uv[TP*128];             // [u(64) | v(64)] per point
__device__ float    g_xc[TP*192];
__device__ float    g_sq[TP];
__device__ unsigned g_gm[NB*1024];
__device__ float    g_c1[NB*256];
__device__ float    g_h1[(size_t)TP*256];
__device__ float    g_h2[(size_t)TP*256];
__device__ float    g_h3[(size_t)TP*128];
__device__ float    g_wad3[128*64], g_bv3[128];
__device__ float    g_wad5[128*64], g_bv5[128];
__device__ float    g_wt[1088*256];

__device__ __forceinline__ float lrelu_f(float x){ return fmaxf(x, SLP*x); }
__device__ __forceinline__ unsigned fenc(float f){
    unsigned u = __float_as_uint(f);
    return u ^ (unsigned)(((int)u >> 31) | 0x80000000);
}
__device__ __forceinline__ float fdec(unsigned e){
    return __uint_as_float((e & 0x80000000u) ? (e & 0x7FFFFFFFu) : ~e);
}

// ------------- symmetric distance GEMM -> encoded keys, upper-triangle blocks ------------
__global__ void __launch_bounds__(256,2) dist_gemm_sym(const float* __restrict__ X, int lda,
                                                       unsigned* __restrict__ Dm)
{
    __shared__ __align__(16) float As[16][128];
    __shared__ __align__(16) float Bs[16][128];
    __shared__ unsigned T[32][129];
    const int tid = threadIdx.x, z = blockIdx.z;
    const int t = blockIdx.x;
    int bj = (int)((sqrtf(8.f*(float)t + 1.f) - 1.f) * 0.5f);
    while ((bj+1)*(bj+2)/2 <= t) bj++;
    while (bj*(bj+1)/2 > t) bj--;
    const int bi = t - bj*(bj+1)/2;                 // bi <= bj
    const int m0 = bi<<7, n0 = bj<<7;
    const float* Xb = X + (size_t)z*NP*lda;
    const int lr = tid>>1, lc = (tid&1)<<3;
    const float* Arow = Xb + (size_t)(m0+lr)*lda + lc;
    const float* Brow = Xb + (size_t)(n0+lr)*lda + lc;
    const int tx = tid&15, ty = tid>>4;
    float acc[8][8] = {};
    for (int kc=0; kc<64; kc+=16){
        float4 a0 = *(const float4*)(Arow+kc);
        float4 a1 = *(const float4*)(Arow+kc+4);
        float4 b0 = *(const float4*)(Brow+kc);
        float4 b1 = *(const float4*)(Brow+kc+4);
        As[lc+0][lr]=a0.x; As[lc+1][lr]=a0.y; As[lc+2][lr]=a0.z; As[lc+3][lr]=a0.w;
        As[lc+4][lr]=a1.x; As[lc+5][lr]=a1.y; As[lc+6][lr]=a1.z; As[lc+7][lr]=a1.w;
        Bs[lc+0][lr]=b0.x; Bs[lc+1][lr]=b0.y; Bs[lc+2][lr]=b0.z; Bs[lc+3][lr]=b0.w;
        Bs[lc+4][lr]=b1.x; Bs[lc+5][lr]=b1.y; Bs[lc+6][lr]=b1.z; Bs[lc+7][lr]=b1.w;
        __syncthreads();
        #pragma unroll
        for (int kk=0; kk<16; kk++){
            float4 x0 = *(const float4*)&As[kk][ty<<3];
            float4 x1 = *(const float4*)&As[kk][(ty<<3)+4];
            float4 y0 = *(const float4*)&Bs[kk][tx<<3];
            float4 y1 = *(const float4*)&Bs[kk][(tx<<3)+4];
            float ar[8]={x0.x,x0.y,x0.z,x0.w,x1.x,x1.y,x1.z,x1.w};
            float br[8]={y0.x,y0.y,y0.z,y0.w,y1.x,y1.y,y1.z,y1.w};
            #pragma unroll
            for (int i=0;i<8;i++)
                #pragma unroll
                for (int j=0;j<8;j++) acc[i][j] = fmaf(ar[i], br[j], acc[i][j]);
        }
        __syncthreads();
    }
    const float* sqb = g_sq + z*NP;
    unsigned* Db = Dm + (size_t)z*NP*NP;
    float sc[8];
    #pragma unroll
    for (int j=0;j<8;j++) sc[j] = sqb[n0 + (tx<<3) + j];
    #pragma unroll
    for (int i=0;i<8;i++){
        int r = m0 + (ty<<3) + i;
        float sr = sqb[r];
        uint4 v0, v1;
        v0.x=fenc(2.f*acc[i][0]-sr-sc[0]); v0.y=fenc(2.f*acc[i][1]-sr-sc[1]);
        v0.z=fenc(2.f*acc[i][2]-sr-sc[2]); v0.w=fenc(2.f*acc[i][3]-sr-sc[3]);
        v1.x=fenc(2.f*acc[i][4]-sr-sc[4]); v1.y=fenc(2.f*acc[i][5]-sr-sc[5]);
        v1.z=fenc(2.f*acc[i][6]-sr-sc[6]); v1.w=fenc(2.f*acc[i][7]-sr-sc[7]);
        *(uint4*)&Db[(size_t)r*NP + n0 + (tx<<3)]     = v0;
        *(uint4*)&Db[(size_t)r*NP + n0 + (tx<<3) + 4] = v1;
    }
    if (bi == bj) return;
    const int r_m = tid>>1, h = tid&1;
    for (int c=0; c<4; c++){
        __syncthreads();
        if ((ty>>2) == c){
            int rloc = (ty&3)<<3;
            #pragma unroll
            for (int i=0;i<8;i++){
                float sri = sqb[m0 + (ty<<3) + i];
                #pragma unroll
                for (int j=0;j<8;j++)
                    T[rloc+i][(tx<<3)+j] = fenc(2.f*acc[i][j]-sri-sc[j]);
            }
        }
        __syncthreads();
        unsigned* dst = &Db[(size_t)(n0+r_m)*NP + m0 + (c<<5) + (h<<4)];
        uint4 w0, w1, w2, w3;
        int rb = h<<4;
        w0.x=T[rb+ 0][r_m]; w0.y=T[rb+ 1][r_m]; w0.z=T[rb+ 2][r_m]; w0.w=T[rb+ 3][r_m];
        w1.x=T[rb+ 4][r_m]; w1.y=T[rb+ 5][r_m]; w1.z=T[rb+ 6][r_m]; w1.w=T[rb+ 7][r_m];
        w2.x=T[rb+ 8][r_m]; w2.y=T[rb+ 9][r_m]; w2.z=T[rb+10][r_m]; w2.w=T[rb+11][r_m];
        w3.x=T[rb+12][r_m]; w3.y=T[rb+13][r_m]; w3.z=T[rb+14][r_m]; w3.w=T[rb+15][r_m];
        ((uint4*)dst)[0]=w0; ((uint4*)dst)[1]=w1; ((uint4*)dst)[2]=w2; ((uint4*)dst)[3]=w3;
    }
}

// ------------------- generic 128x128 GEMM: C = epi(A * B^T) ------------------------------
// MODE 1: +bias[col]   2: lrelu(+bias[col])   3: lrelu(+bias[batch*ncols+col])
// MODE 5: atomicMax(gmax[batch*ncols+col], enc(lrelu(acc+bias[col])))   (no C write)
template<int MODE>
__global__ void __launch_bounds__(256,2) gemm_big(
    const float* __restrict__ A, int lda, const float* __restrict__ B, int ldb,
    float* __restrict__ C, int ldc, int K,
    const float* __restrict__ bias, unsigned* __restrict__ gmax, int ncols)
{
    __shared__ __align__(16) float As[16][128];
    __shared__ __align__(16) float Bs[16][128];
    __shared__ unsigned gred[128];
    const int tid = threadIdx.x;
    const int m0 = blockIdx.y*128, n0 = blockIdx.x*128;
    const int lr = tid>>1, lc = (tid&1)<<3;
    const float* Arow = A + (size_t)(m0+lr)*lda + lc;
    const float* Brow = B + (size_t)(n0+lr)*ldb + lc;
    const int tx = tid&15, ty = tid>>4;
    float acc[8][8] = {};
    for (int kc=0; kc<K; kc+=16){
        float4 a0 = *(const float4*)(Arow+kc);
        float4 a1 = *(const float4*)(Arow+kc+4);
        float4 b0 = *(const float4*)(Brow+kc);
        float4 b1 = *(const float4*)(Brow+kc+4);
        As[lc+0][lr]=a0.x; As[lc+1][lr]=a0.y; As[lc+2][lr]=a0.z; As[lc+3][lr]=a0.w;
        As[lc+4][lr]=a1.x; As[lc+5][lr]=a1.y; As[lc+6][lr]=a1.z; As[lc+7][lr]=a1.w;
        Bs[lc+0][lr]=b0.x; Bs[lc+1][lr]=b0.y; Bs[lc+2][lr]=b0.z; Bs[lc+3][lr]=b0.w;
        Bs[lc+4][lr]=b1.x; Bs[lc+5][lr]=b1.y; Bs[lc+6][lr]=b1.z; Bs[lc+7][lr]=b1.w;
        __syncthreads();
        #pragma unroll
        for (int kk=0; kk<16; kk++){
            float4 x0 = *(const float4*)&As[kk][ty<<3];
            float4 x1 = *(const float4*)&As[kk][(ty<<3)+4];
            float4 y0 = *(const float4*)&Bs[kk][tx<<3];
            float4 y1 = *(const float4*)&Bs[kk][(tx<<3)+4];
            float ar[8]={x0.x,x0.y,x0.z,x0.w,x1.x,x1.y,x1.z,x1.w};
            float br[8]={y0.x,y0.y,y0.z,y0.w,y1.x,y1.y,y1.z,y1.w};
            #pragma unroll
            for (int i=0;i<8;i++)
                #pragma unroll
                for (int j=0;j<8;j++) acc[i][j] = fmaf(ar[i], br[j], acc[i][j]);
        }
        __syncthreads();
    }
    if (MODE==5){
        if (tid<128) gred[tid]=0u;
        __syncthreads();
        #pragma unroll
        for (int j=0;j<8;j++){
            int c = (tx<<3)+j;
            float bb = bias[n0+c];
            float m = -3.4e38f;
            #pragma unroll
            for (int i=0;i<8;i++) m = fmaxf(m, lrelu_f(acc[i][j]+bb));
            atomicMax(&gred[c], fenc(m));
        }
        __syncthreads();
        if (tid<128){
            int bb = m0 >> 12;
            atomicMax(&gmax[bb*ncols + n0 + tid], gred[tid]);
        }
        return;
    }
    #pragma unroll
    for (int i=0;i<8;i++){
        int r = m0 + (ty<<3) + i;
        float4 v0, v1;
        #pragma unroll
        for (int j=0;j<8;j++){
            int c = n0 + (tx<<3) + j;
            float val = acc[i][j];
            if (MODE==1 || MODE==2) val += bias[c];
            if (MODE==3)            val += bias[(m0>>12)*ncols + c];
            if (MODE==2 || MODE==3) val = lrelu_f(val);
            if (j<4) ((float*)&v0)[j] = val; else ((float*)&v1)[j-4] = val;
        }
        *(float4*)&C[(size_t)r*ldc + n0 + (tx<<3)]     = v0;
        *(float4*)&C[(size_t)r*ldc + n0 + (tx<<3) + 4] = v1;
    }
}

// ------------------- fused edge GEMM + per-point max (global REDG) -----------------------
__global__ void __launch_bounds__(256,2) edge_gemm(
    const float* __restrict__ UV,
    const int* __restrict__ IDX, const float* __restrict__ W,
    const float* __restrict__ bias, unsigned* __restrict__ Xout, int ldx)
{
    __shared__ __align__(16) float As[16][128];
    __shared__ __align__(16) float Bs[16][64];
    const int tid = threadIdx.x;
    const int m0 = blockIdx.x*128;
    const int lr = tid>>1, lc = (tid&1)<<3;
    const int e  = m0 + lr;
    const int p  = e / KN;
    const int jg = IDX[e];
    const float* urow = UV + (size_t)jg*128 + lc;
    const float* vrow = UV + (size_t)p *128 + 64 + lc;
    const int lrB = tid>>2, lcB = (tid&3)<<2;
    const float* wrow = W + lrB*64 + lcB;
    const int tx = tid&15, ty = tid>>4;
    float acc[8][4] = {};
    #pragma unroll
    for (int kc=0; kc<64; kc+=16){
        float4 u0=*(const float4*)(urow+kc), u1=*(const float4*)(urow+kc+4);
        float4 v0=*(const float4*)(vrow+kc), v1=*(const float4*)(vrow+kc+4);
        float4 w4=*(const float4*)(wrow+kc);
        As[lc+0][lr]=lrelu_f(u0.x+v0.x); As[lc+1][lr]=lrelu_f(u0.y+v0.y);
        As[lc+2][lr]=lrelu_f(u0.z+v0.z); As[lc+3][lr]=lrelu_f(u0.w+v0.w);
        As[lc+4][lr]=lrelu_f(u1.x+v1.x); As[lc+5][lr]=lrelu_f(u1.y+v1.y);
        As[lc+6][lr]=lrelu_f(u1.z+v1.z); As[lc+7][lr]=lrelu_f(u1.w+v1.w);
        Bs[lcB+0][lrB]=w4.x; Bs[lcB+1][lrB]=w4.y; Bs[lcB+2][lrB]=w4.z; Bs[lcB+3][lrB]=w4.w;
        __syncthreads();
        #pragma unroll
        for (int kk=0; kk<16; kk++){
            float4 x0 = *(const float4*)&As[kk][ty<<3];
            float4 x1 = *(const float4*)&As[kk][(ty<<3)+4];
            float4 y0 = *(const float4*)&Bs[kk][tx<<2];
            float ar[8]={x0.x,x0.y,x0.z,x0.w,x1.x,x1.y,x1.z,x1.w};
            float br[4]={y0.x,y0.y,y0.z,y0.w};
            #pragma unroll
            for (int i=0;i<8;i++)
                #pragma unroll
                for (int j=0;j<4;j++) acc[i][j] = fmaf(ar[i], br[j], acc[i][j]);
        }
        __syncthreads();
    }
    const int e0 = m0 + (ty<<3);
    const int p0 = e0 / KN;
    const int p7 = (e0+7) / KN;
    const int s  = (p7 != p0) ? (p7*KN - e0) : 8;
    #pragma unroll
    for (int j=0;j<4;j++){
        int c = (tx<<2)+j;
        float bb = bias[c];
        float mA = -3.4e38f, mB = -3.4e38f;
        #pragma unroll
        for (int i=0;i<8;i++){
            float v = lrelu_f(acc[i][j]+bb);
            if (i < s) mA = fmaxf(mA, v); else mB = fmaxf(mB, v);
        }
        atomicMax(&Xout[(size_t)p0*ldx + c], fenc(mA));
        if (p7 != p0) atomicMax(&Xout[(size_t)p7*ldx + c], fenc(mB));
    }
}

// ------------------- exact top-40 radix select: geometry variant (smem keys) -------------
__global__ void __launch_bounds__(256) topk40_geo(
    const float* __restrict__ P3, const float* __restrict__ sqv, int* __restrict__ OUT)
{
    __shared__ unsigned keys[NP];
    __shared__ int hist[256];
    __shared__ unsigned short cbuf[2][NP];
    __shared__ int warptot[8];
    __shared__ int s_dsel, s_r, s_cout, s_cnc;
    const int row = blockIdx.x, tid = threadIdx.x;
    const int lane = tid & 31, wrp = tid >> 5;
    const int base = (row >> 12) << 12;
    hist[tid] = 0;
    if (tid == 0){ s_r = KN; s_cout = 0; s_cnc = 0; }
    __syncthreads();
    {
        const float x0=P3[(size_t)row*3], x1=P3[(size_t)row*3+1], x2=P3[(size_t)row*3+2];
        const float sn = sqv[row];
        for (int i = tid; i < NP; i += 256){
            const float* pm = P3 + (size_t)(base+i)*3;
            float d = 2.f*(x0*pm[0]+x1*pm[1]+x2*pm[2]) - sn - sqv[base+i];
            unsigned kx = fenc(d);
            keys[i] = kx;
            int dig = kx >> 24;
            unsigned mm = __match_any_sync(FULLM, dig);
            if ((__ffs(mm)-1) == lane) atomicAdd(&hist[dig], __popc(mm));
        }
    }
    __syncthreads();
    int n_cur = NP, cur = 0;
    for (int pass = 3; pass >= 0; pass--){
        const int sh = pass << 3;
        {
            int val = hist[tid];
            int r_cur = s_r;
            int s = val;
            #pragma unroll
            for (int d=1; d<32; d<<=1){
                int t = __shfl_down_sync(FULLM, s, d);
                if (lane + d < 32) s += t;
            }
            if (lane == 0) warptot[wrp] = s;
            __syncthreads();
            int offs = 0;
            #pragma unroll
            for (int w=0; w<8; w++) if (w > wrp) offs += warptot[w];
            int S = s + offs;
            if (S >= r_cur && S - val < r_cur){ s_dsel = tid; s_r = r_cur - (S - val); }
            __syncthreads();
        }
        const int dsel = s_dsel;
        hist[tid] = 0;
        if (tid == 0) s_cnc = 0;
        __syncthreads();
        const int nt = (n_cur + 255) >> 8;
        for (int it = 0; it < nt; it++){
            int ii = it*256 + tid;
            bool vld = ii < n_cur;
            int gi = 0; unsigned kx = 0;
            if (vld){
                gi = (pass==3) ? ii : (int)cbuf[cur][ii];
                kx = keys[gi];
            }
            int dig = vld ? (int)((kx >> sh) & 255) : 0x1FF;
            bool gt = vld && dig > dsel;
            bool eq = vld && dig == dsel;
            unsigned bg = __ballot_sync(FULLM, gt);
            unsigned be = __ballot_sync(FULLM, eq);
            int baseg = 0, basee = 0;
            if (lane == 0){
                if (bg) baseg = atomicAdd(&s_cout, __popc(bg));
                if (be) basee = atomicAdd(&s_cnc, __popc(be));
            }
            baseg = __shfl_sync(FULLM, baseg, 0);
            basee = __shfl_sync(FULLM, basee, 0);
            unsigned ltm = (1u << lane) - 1u;
            if (gt) OUT[row*KN + baseg + __popc(bg & ltm)] = base + gi;
            if (eq) cbuf[cur^1][basee + __popc(be & ltm)] = (unsigned short)gi;
        }
        __syncthreads();
        n_cur = s_cnc;
        cur ^= 1;
        if (pass > 0){
            const int sh2 = sh - 8;
            const int nt2 = (n_cur + 255) >> 8;
            for (int it = 0; it < nt2; it++){
                int ii = it*256 + tid;
                bool vld = ii < n_cur;
                int dig = 0x1FF;
                if (vld) dig = (keys[cbuf[cur][ii]] >> sh2) & 255;
                unsigned mm = __match_any_sync(FULLM, dig);
                if (vld && (__ffs(mm)-1) == lane) atomicAdd(&hist[dig], __popc(mm));
            }
            __syncthreads();
        }
    }
    if (tid == 0){
        int need = s_r, cw = s_cout;
        int cnt = n_cur;
        for (int s = 0; s < need; s++){
            int bi=-1, bv=1<<30;
            for (int q=0; q<cnt; q++){ int v = cbuf[cur][q]; if (v < bv){ bv=v; bi=q; } }
            OUT[row*KN + cw + s] = base + bv;
            if (bi >= 0) cbuf[cur][bi] = 0xFFFF;
        }
    }
}

// ------------------- exact top-40 radix select: DK variant (keys stay in L2) -------------
__global__ void __launch_bounds__(256) topk40_dk(
    const unsigned* __restrict__ DK, int* __restrict__ OUT)
{
    __shared__ int hist[256];
    __shared__ unsigned short cbuf[2][NP];
    __shared__ int warptot[8];
    __shared__ int s_dsel, s_r, s_cout, s_cnc;
    const int row = blockIdx.x, tid = threadIdx.x;
    const int lane = tid & 31, wrp = tid >> 5;
    const int base = (row >> 12) << 12;
    const unsigned* drow = DK + (size_t)row*NP;
    hist[tid] = 0;
    if (tid == 0){ s_r = KN; s_cout = 0; s_cnc = 0; }
    __syncthreads();
    for (int i = tid; i < NP; i += 256){
        unsigned kx = __ldg(&drow[i]);
        int dig = kx >> 24;
        unsigned mm = __match_any_sync(FULLM, dig);
        if ((__ffs(mm)-1) == lane) atomicAdd(&hist[dig], __popc(mm));
    }
    __syncthreads();
    int n_cur = NP, cur = 0;
    for (int pass = 3; pass >= 0; pass--){
        const int sh = pass << 3;
        {
            int val = hist[tid];
            int r_cur = s_r;
            int s = val;
            #pragma unroll
            for (int d=1; d<32; d<<=1){
                int t = __shfl_down_sync(FULLM, s, d);
                if (lane + d < 32) s += t;
            }
            if (lane == 0) warptot[wrp] = s;
            __syncthreads();
            int offs = 0;
            #pragma unroll
            for (int w=0; w<8; w++) if (w > wrp) offs += warptot[w];
            int S = s + offs;
            if (S >= r_cur && S - val < r_cur){ s_dsel = tid; s_r = r_cur - (S - val); }
            __syncthreads();
        }
        const int dsel = s_dsel;
        hist[tid] = 0;
        if (tid == 0) s_cnc = 0;
        __syncthreads();
        const int nt = (n_cur + 255) >> 8;
        for (int it = 0; it < nt; it++){
            int ii = it*256 + tid;
            bool vld = ii < n_cur;
            int gi = 0; unsigned kx = 0;
            if (vld){
                gi = (pass==3) ? ii : (int)cbuf[cur][ii];
                kx = __ldg(&drow[gi]);
            }
            int dig = vld ? (int)((kx >> sh) & 255) : 0x1FF;
            bool gt = vld && dig > dsel;
            bool eq = vld && dig == dsel;
            unsigned bg = __ballot_sync(FULLM, gt);
            unsigned be = __ballot_sync(FULLM, eq);
            int baseg = 0, basee = 0;
            if (lane == 0){
                if (bg) baseg = atomicAdd(&s_cout, __popc(bg));
                if (be) basee = atomicAdd(&s_cnc, __popc(be));
            }
            baseg = __shfl_sync(FULLM, baseg, 0);
            basee = __shfl_sync(FULLM, basee, 0);
            unsigned ltm = (1u << lane) - 1u;
            if (gt) OUT[row*KN + baseg + __popc(bg & ltm)] = base + gi;
            if (eq) cbuf[cur^1][basee + __popc(be & ltm)] = (unsigned short)gi;
        }
        __syncthreads();
        n_cur = s_cnc;
        cur ^= 1;
        if (pass > 0){
            const int sh2 = sh - 8;
            const int nt2 = (n_cur + 255) >> 8;
            for (int it = 0; it < nt2; it++){
                int ii = it*256 + tid;
                bool vld = ii < n_cur;
                int dig = 0x1FF;
                if (vld) dig = (__ldg(&drow[cbuf[cur][ii]]) >> sh2) & 255;
                unsigned mm = __match_any_sync(FULLM, dig);
                if (vld && (__ffs(mm)-1) == lane) atomicAdd(&hist[dig], __popc(mm));
            }
            __syncthreads();
        }
    }
    if (tid == 0){
        int need = s_r, cw = s_cout;
        int cnt = n_cur;
        for (int s = 0; s < need; s++){
            int bi=-1, bv=1<<30;
            for (int q=0; q<cnt; q++){ int v = cbuf[cur][q]; if (v < bv){ bv=v; bi=q; } }
            OUT[row*KN + cw + s] = base + bv;
            if (bi >= 0) cbuf[cur][bi] = 0xFFFF;
        }
    }
}

// ----------------------------- small kernels ---------------------------------------------
__global__ void sqnormk(const float* __restrict__ X, int ld, int C){
    int p = blockIdx.x*256 + threadIdx.x;
    if (p>=TP) return;
    const float* r = X + (size_t)p*ld;
    float s=0.f;
    for (int c=0;c<C;c++) s = fmaf(r[c],r[c],s);
    g_sq[p]=s;
}
__global__ void uv1k(const float* __restrict__ P, const float* __restrict__ W1, const float* __restrict__ b1){
    int g = blockIdx.x*256 + threadIdx.x;
    int o = g&63, p = g>>6;
    const float* x = P + (size_t)p*3;
    float u=0.f, v=b1[o];
    #pragma unroll
    for (int c=0;c<3;c++){
        float wa=W1[o*6+c], wb=W1[o*6+3+c];
        u = fmaf(wa, x[c], u);
        v = fmaf(wb-wa, x[c], v);
    }
    g_uv[(size_t)p*128 + o]      = u;
    g_uv[(size_t)p*128 + 64 + o] = v;
}
__global__ void wprep2k(const float* __restrict__ W, const float* __restrict__ b,
                        float* __restrict__ wad, float* __restrict__ bv){
    int g = blockIdx.x*256 + threadIdx.x;
    if (g < 8192){
        int o = g>>6, c = g&63;
        float val;
        if (o < 64) val = W[o*128 + c];
        else        val = W[(o-64)*128 + 64 + c] - W[(o-64)*128 + c];
        wad[g] = val;
    }
    if (g < 128) bv[g] = (g < 64) ? 0.f : b[g-64];
}
__global__ void initenck(int off){
    int g = blockIdx.x*256 + threadIdx.x;
    int p=g>>6, c=g&63;
    ((unsigned*)g_xc)[(size_t)p*192 + off + c]=0u;
}
__global__ void decenck(int off){
    int g = blockIdx.x*256 + threadIdx.x;
    int p=g>>6, c=g&63;
    size_t ix=(size_t)p*192 + off + c;
    unsigned e = ((unsigned*)g_xc)[ix];
    g_xc[ix]=fdec(e);
}
__global__ void initgk(){ int g=blockIdx.x*256+threadIdx.x; if (g<NB*1024) g_gm[g]=0u; }
__global__ void maxedgek(){
    int p = blockIdx.x, o = threadIdx.x;
    float v = g_uv[(size_t)p*128 + 64 + o];
    float best = -3.4e38f;
    #pragma unroll 4
    for (int j=0;j<KN;j++){
        int jg = g_idx[p*KN+j];
        best = fmaxf(best, lrelu_f(g_uv[(size_t)jg*128 + o] + v));
    }
    g_xc[(size_t)p*192 + 128 + o] = best;
}
__global__ void wp1tk(const float* __restrict__ Wp1){
    int g = blockIdx.x*256 + threadIdx.x;
    if (g >= 1088*256) return;
    int o = g&255, j = g>>8;
    g_wt[(size_t)j*256 + o] = Wp1[(size_t)o*1280 + 192 + j];
}
__global__ void __launch_bounds__(256) globk(
    const float* __restrict__ label, const float* __restrict__ W7,
    const float* __restrict__ b7, const float* __restrict__ bp1)
{
    __shared__ float gl[1088];
    int b = blockIdx.x, tid = threadIdx.x;
    for (int i=tid;i<1024;i+=256) gl[i]=fdec(g_gm[b*1024+i]);
    if (tid<64){
        float a=b7[tid];
        #pragma unroll
        for (int c=0;c<16;c++) a = fmaf(label[b*16+c], W7[tid*16+c], a);
        gl[1024+tid]=lrelu_f(a);
    }
    __syncthreads();
    float a = bp1[tid];
    #pragma unroll 8
    for (int j=0;j<1088;j++) a = fmaf(g_wt[(size_t)j*256 + tid], gl[j], a);
    g_c1[b*256+tid]=a;
}
__global__ void outk(const float* __restrict__ Wp4, float* __restrict__ out){
    int g = blockIdx.x*256 + threadIdx.x;
    int s = g%6, p = g/6;
    const float* h = g_h3 + (size_t)p*128;
    const float* w = Wp4 + s*128;
    float a=0.f;
    #pragma unroll 8
    for (int c=0;c<128;c++) a = fmaf(h[c], w[c], a);
    out[g]=a;
}

// ----------------------------- host ------------------------------------------------------
static void* symaddr(const void* s){ void* p=nullptr; cudaGetSymbolAddress(&p, s); return p; }

extern "C" void kernel_launch(void* const* d_in, const int* in_sizes, int n_in,
                              void* d_out, int out_size)
{
    const float* points=(const float*)d_in[0];
    const float* label =(const float*)d_in[1];
    const float *W1=(const float*)d_in[2],  *b1=(const float*)d_in[3];
    const float *W2=(const float*)d_in[4],  *b2=(const float*)d_in[5];
    const float *W3=(const float*)d_in[6],  *b3=(const float*)d_in[7];
    const float *W4=(const float*)d_in[8],  *b4=(const float*)d_in[9];
    const float *W5=(const float*)d_in[10], *b5=(const float*)d_in[11];
    const float *W6=(const float*)d_in[12], *b6=(const float*)d_in[13];
    const float *W7=(const float*)d_in[14], *b7=(const float*)d_in[15];
    const float *Wp1=(const float*)d_in[16],*bp1=(const float*)d_in[17];
    const float *Wp2=(const float*)d_in[18],*bp2=(const float*)d_in[19];
    const float *Wp3=(const float*)d_in[20],*bp3=(const float*)d_in[21];
    const float *Wp4=(const float*)d_in[22];
    float* out=(float*)d_out;

    unsigned* pDK =(unsigned*)symaddr(g_DK);
    int*      pIdx=(int*)     symaddr(g_idx);
    float*    pUV =(float*)   symaddr(g_uv);
    float*    pXc =(float*)   symaddr(g_xc);
    float*    pSq =(float*)   symaddr(g_sq);
    unsigned* pGm =(unsigned*)symaddr(g_gm);
    float*    pC1 =(float*)   symaddr(g_c1);
    float*    pH1 =(float*)   symaddr(g_h1);
    float*    pH2 =(float*)   symaddr(g_h2);
    float*    pH3 =(float*)   symaddr(g_h3);
    float*    pWad3=(float*)  symaddr(g_wad3);
    float*    pBv3 =(float*)  symaddr(g_bv3);
    float*    pWad5=(float*)  symaddr(g_wad5);
    float*    pBv5 =(float*)  symaddr(g_bv5);

    // launches 1-3 prep; launch 4 = topk40_geo for ncu
    sqnormk<<<64,256>>>(points,3,3);
    wprep2k<<<32,256>>>(W3,b3,pWad3,pBv3);
    wprep2k<<<32,256>>>(W5,b5,pWad5,pBv5);
    topk40_geo<<<TP,256>>>(points, pSq, pIdx);
    wp1tk<<<1088,256>>>(Wp1);
    initgk<<<16,256>>>();

    // ---------- EdgeConv block 1 ----------
    uv1k<<<4096,256>>>(points,W1,b1);
    initenck<<<4096,256>>>(0);
    edge_gemm<<<NE/128,256>>>(pUV,pIdx,W2,b2,(unsigned*)pXc+0,192);
    decenck<<<4096,256>>>(0);

    // ---------- EdgeConv block 2 ----------
    sqnormk<<<64,256>>>(pXc+0,192,64);
    dist_gemm_sym<<<dim3(528,1,NB),256>>>(pXc+0,192,pDK);
    topk40_dk<<<TP,256>>>(pDK, pIdx);
    gemm_big<1><<<dim3(1,128),256>>>(pXc+0,192, pWad3,64, pUV,128, 64, pBv3,nullptr,0);
    initenck<<<4096,256>>>(64);
    edge_gemm<<<NE/128,256>>>(pUV,pIdx,W4,b4,(unsigned*)pXc+64,192);
    decenck<<<4096,256>>>(64);

    // ---------- EdgeConv block 3 (single layer -> gather/max) ----------
    sqnormk<<<64,256>>>(pXc+64,192,64);
    dist_gemm_sym<<<dim3(528,1,NB),256>>>(pXc+64,192,pDK);
    topk40_dk<<<TP,256>>>(pDK, pIdx);
    gemm_big<1><<<dim3(1,128),256>>>(pXc+64,192, pWad5,64, pUV,128, 64, pBv5,nullptr,0);
    maxedgek<<<TP,64>>>();

    // ---------- global feature ----------
    gemm_big<5><<<dim3(8,128),256>>>(pXc,192, W6,192, nullptr,0, 192, b6,pGm,1024);
    globk<<<NB,256>>>(label,W7,b7,bp1);

    // ---------- segmentation head ----------
    gemm_big<3><<<dim3(2,128),256>>>(pXc,192, Wp1,1280, pH1,256, 192, pC1,nullptr,256);
    gemm_big<2><<<dim3(2,128),256>>>(pH1,256, Wp2,256,  pH2,256, 256, bp2,nullptr,0);
    gemm_big<2><<<dim3(1,128),256>>>(pH2,256, Wp3,256,  pH3,128, 256, bp3,nullptr,0);
    outk<<<384,256>>>(Wp4,out);
}

// round 17
// speedup vs baseline: 1.4182x; 1.0425x over previous
#include <cuda_runtime.h>

#define NB 4
#define NP 4096
#define TP (NB*NP)
#define KN 40
#define NE (TP*KN)
#define SLP 0.2f
#define FULLM 0xffffffffu

// ----------------------------- scratch -----------------------------
__device__ unsigned g_DK[(size_t)NB*NP*NP];   // encoded distance keys
__device__ int      g_idx[NE];
__device__ float    g_uv[TP*128];             // [u(64) | v(64)] per point
__device__ float    g_xc[TP*192];
__device__ float    g_sq[TP];
__device__ float4   g_p4[TP];                 // (x,y,z,||x||^2) packed
__device__ unsigned g_gm[NB*1024];
__device__ float    g_c1[NB*256];
__device__ float    g_h1[(size_t)TP*256];
__device__ float    g_h2[(size_t)TP*256];
__device__ float    g_h3[(size_t)TP*128];
__device__ float    g_wad3[128*64], g_bv3[128];
__device__ float    g_wad5[128*64], g_bv5[128];
__device__ float    g_wt[1088*256];

__device__ __forceinline__ float lrelu_f(float x){ return fmaxf(x, SLP*x); }
__device__ __forceinline__ unsigned fenc(float f){
    unsigned u = __float_as_uint(f);
    return u ^ (unsigned)(((int)u >> 31) | 0x80000000);
}
__device__ __forceinline__ float fdec(unsigned e){
    return __uint_as_float((e & 0x80000000u) ? (e & 0x7FFFFFFFu) : ~e);
}

// ------------- symmetric distance GEMM -> encoded keys, upper-triangle blocks ------------
__global__ void __launch_bounds__(256,2) dist_gemm_sym(const float* __restrict__ X, int lda,
                                                       unsigned* __restrict__ Dm)
{
    __shared__ __align__(16) float As[16][128];
    __shared__ __align__(16) float Bs[16][128];
    __shared__ unsigned T[32][129];
    const int tid = threadIdx.x, z = blockIdx.z;
    const int t = blockIdx.x;
    int bj = (int)((sqrtf(8.f*(float)t + 1.f) - 1.f) * 0.5f);
    while ((bj+1)*(bj+2)/2 <= t) bj++;
    while (bj*(bj+1)/2 > t) bj--;
    const int bi = t - bj*(bj+1)/2;                 // bi <= bj
    const int m0 = bi<<7, n0 = bj<<7;
    const float* Xb = X + (size_t)z*NP*lda;
    const int lr = tid>>1, lc = (tid&1)<<3;
    const float* Arow = Xb + (size_t)(m0+lr)*lda + lc;
    const float* Brow = Xb + (size_t)(n0+lr)*lda + lc;
    const int tx = tid&15, ty = tid>>4;
    float acc[8][8] = {};
    for (int kc=0; kc<64; kc+=16){
        float4 a0 = *(const float4*)(Arow+kc);
        float4 a1 = *(const float4*)(Arow+kc+4);
        float4 b0 = *(const float4*)(Brow+kc);
        float4 b1 = *(const float4*)(Brow+kc+4);
        As[lc+0][lr]=a0.x; As[lc+1][lr]=a0.y; As[lc+2][lr]=a0.z; As[lc+3][lr]=a0.w;
        As[lc+4][lr]=a1.x; As[lc+5][lr]=a1.y; As[lc+6][lr]=a1.z; As[lc+7][lr]=a1.w;
        Bs[lc+0][lr]=b0.x; Bs[lc+1][lr]=b0.y; Bs[lc+2][lr]=b0.z; Bs[lc+3][lr]=b0.w;
        Bs[lc+4][lr]=b1.x; Bs[lc+5][lr]=b1.y; Bs[lc+6][lr]=b1.z; Bs[lc+7][lr]=b1.w;
        __syncthreads();
        #pragma unroll
        for (int kk=0; kk<16; kk++){
            float4 x0 = *(const float4*)&As[kk][ty<<3];
            float4 x1 = *(const float4*)&As[kk][(ty<<3)+4];
            float4 y0 = *(const float4*)&Bs[kk][tx<<3];
            float4 y1 = *(const float4*)&Bs[kk][(tx<<3)+4];
            float ar[8]={x0.x,x0.y,x0.z,x0.w,x1.x,x1.y,x1.z,x1.w};
            float br[8]={y0.x,y0.y,y0.z,y0.w,y1.x,y1.y,y1.z,y1.w};
            #pragma unroll
            for (int i=0;i<8;i++)
                #pragma unroll
                for (int j=0;j<8;j++) acc[i][j] = fmaf(ar[i], br[j], acc[i][j]);
        }
        __syncthreads();
    }
    const float* sqb = g_sq + z*NP;
    unsigned* Db = Dm + (size_t)z*NP*NP;
    float sc[8];
    #pragma unroll
    for (int j=0;j<8;j++) sc[j] = sqb[n0 + (tx<<3) + j];
    #pragma unroll
    for (int i=0;i<8;i++){
        int r = m0 + (ty<<3) + i;
        float sr = sqb[r];
        uint4 v0, v1;
        v0.x=fenc(2.f*acc[i][0]-sr-sc[0]); v0.y=fenc(2.f*acc[i][1]-sr-sc[1]);
        v0.z=fenc(2.f*acc[i][2]-sr-sc[2]); v0.w=fenc(2.f*acc[i][3]-sr-sc[3]);
        v1.x=fenc(2.f*acc[i][4]-sr-sc[4]); v1.y=fenc(2.f*acc[i][5]-sr-sc[5]);
        v1.z=fenc(2.f*acc[i][6]-sr-sc[6]); v1.w=fenc(2.f*acc[i][7]-sr-sc[7]);
        *(uint4*)&Db[(size_t)r*NP + n0 + (tx<<3)]     = v0;
        *(uint4*)&Db[(size_t)r*NP + n0 + (tx<<3) + 4] = v1;
    }
    if (bi == bj) return;
    const int r_m = tid>>1, h = tid&1;
    for (int c=0; c<4; c++){
        __syncthreads();
        if ((ty>>2) == c){
            int rloc = (ty&3)<<3;
            #pragma unroll
            for (int i=0;i<8;i++){
                float sri = sqb[m0 + (ty<<3) + i];
                #pragma unroll
                for (int j=0;j<8;j++)
                    T[rloc+i][(tx<<3)+j] = fenc(2.f*acc[i][j]-sri-sc[j]);
            }
        }
        __syncthreads();
        unsigned* dst = &Db[(size_t)(n0+r_m)*NP + m0 + (c<<5) + (h<<4)];
        uint4 w0, w1, w2, w3;
        int rb = h<<4;
        w0.x=T[rb+ 0][r_m]; w0.y=T[rb+ 1][r_m]; w0.z=T[rb+ 2][r_m]; w0.w=T[rb+ 3][r_m];
        w1.x=T[rb+ 4][r_m]; w1.y=T[rb+ 5][r_m]; w1.z=T[rb+ 6][r_m]; w1.w=T[rb+ 7][r_m];
        w2.x=T[rb+ 8][r_m]; w2.y=T[rb+ 9][r_m]; w2.z=T[rb+10][r_m]; w2.w=T[rb+11][r_m];
        w3.x=T[rb+12][r_m]; w3.y=T[rb+13][r_m]; w3.z=T[rb+14][r_m]; w3.w=T[rb+15][r_m];
        ((uint4*)dst)[0]=w0; ((uint4*)dst)[1]=w1; ((uint4*)dst)[2]=w2; ((uint4*)dst)[3]=w3;
    }
}

// ------------------- generic 128x128 GEMM: C = epi(A * B^T) ------------------------------
template<int MODE>
__global__ void __launch_bounds__(256,2) gemm_big(
    const float* __restrict__ A, int lda, const float* __restrict__ B, int ldb,
    float* __restrict__ C, int ldc, int K,
    const float* __restrict__ bias, unsigned* __restrict__ gmax, int ncols)
{
    __shared__ __align__(16) float As[16][128];
    __shared__ __align__(16) float Bs[16][128];
    __shared__ unsigned gred[128];
    const int tid = threadIdx.x;
    const int m0 = blockIdx.y*128, n0 = blockIdx.x*128;
    const int lr = tid>>1, lc = (tid&1)<<3;
    const float* Arow = A + (size_t)(m0+lr)*lda + lc;
    const float* Brow = B + (size_t)(n0+lr)*ldb + lc;
    const int tx = tid&15, ty = tid>>4;
    float acc[8][8] = {};
    for (int kc=0; kc<K; kc+=16){
        float4 a0 = *(const float4*)(Arow+kc);
        float4 a1 = *(const float4*)(Arow+kc+4);
        float4 b0 = *(const float4*)(Brow+kc);
        float4 b1 = *(const float4*)(Brow+kc+4);
        As[lc+0][lr]=a0.x; As[lc+1][lr]=a0.y; As[lc+2][lr]=a0.z; As[lc+3][lr]=a0.w;
        As[lc+4][lr]=a1.x; As[lc+5][lr]=a1.y; As[lc+6][lr]=a1.z; As[lc+7][lr]=a1.w;
        Bs[lc+0][lr]=b0.x; Bs[lc+1][lr]=b0.y; Bs[lc+2][lr]=b0.z; Bs[lc+3][lr]=b0.w;
        Bs[lc+4][lr]=b1.x; Bs[lc+5][lr]=b1.y; Bs[lc+6][lr]=b1.z; Bs[lc+7][lr]=b1.w;
        __syncthreads();
        #pragma unroll
        for (int kk=0; kk<16; kk++){
            float4 x0 = *(const float4*)&As[kk][ty<<3];
            float4 x1 = *(const float4*)&As[kk][(ty<<3)+4];
            float4 y0 = *(const float4*)&Bs[kk][tx<<3];
            float4 y1 = *(const float4*)&Bs[kk][(tx<<3)+4];
            float ar[8]={x0.x,x0.y,x0.z,x0.w,x1.x,x1.y,x1.z,x1.w};
            float br[8]={y0.x,y0.y,y0.z,y0.w,y1.x,y1.y,y1.z,y1.w};
            #pragma unroll
            for (int i=0;i<8;i++)
                #pragma unroll
                for (int j=0;j<8;j++) acc[i][j] = fmaf(ar[i], br[j], acc[i][j]);
        }
        __syncthreads();
    }
    if (MODE==5){
        if (tid<128) gred[tid]=0u;
        __syncthreads();
        #pragma unroll
        for (int j=0;j<8;j++){
            int c = (tx<<3)+j;
            float bb = bias[n0+c];
            float m = -3.4e38f;
            #pragma unroll
            for (int i=0;i<8;i++) m = fmaxf(m, lrelu_f(acc[i][j]+bb));
            atomicMax(&gred[c], fenc(m));
        }
        __syncthreads();
        if (tid<128){
            int bb = m0 >> 12;
            atomicMax(&gmax[bb*ncols + n0 + tid], gred[tid]);
        }
        return;
    }
    #pragma unroll
    for (int i=0;i<8;i++){
        int r = m0 + (ty<<3) + i;
        float4 v0, v1;
        #pragma unroll
        for (int j=0;j<8;j++){
            int c = n0 + (tx<<3) + j;
            float val = acc[i][j];
            if (MODE==1 || MODE==2) val += bias[c];
            if (MODE==3)            val += bias[(m0>>12)*ncols + c];
            if (MODE==2 || MODE==3) val = lrelu_f(val);
            if (j<4) ((float*)&v0)[j] = val; else ((float*)&v1)[j-4] = val;
        }
        *(float4*)&C[(size_t)r*ldc + n0 + (tx<<3)]     = v0;
        *(float4*)&C[(size_t)r*ldc + n0 + (tx<<3) + 4] = v1;
    }
}

// ------------------- fused edge GEMM + per-point max (global REDG) -----------------------
__global__ void __launch_bounds__(256,2) edge_gemm(
    const float* __restrict__ UV,
    const int* __restrict__ IDX, const float* __restrict__ W,
    const float* __restrict__ bias, unsigned* __restrict__ Xout, int ldx)
{
    __shared__ __align__(16) float As[16][128];
    __shared__ __align__(16) float Bs[16][64];
    const int tid = threadIdx.x;
    const int m0 = blockIdx.x*128;
    const int lr = tid>>1, lc = (tid&1)<<3;
    const int e  = m0 + lr;
    const int p  = e / KN;
    const int jg = IDX[e];
    const float* urow = UV + (size_t)jg*128 + lc;
    const float* vrow = UV + (size_t)p *128 + 64 + lc;
    const int lrB = tid>>2, lcB = (tid&3)<<2;
    const float* wrow = W + lrB*64 + lcB;
    const int tx = tid&15, ty = tid>>4;
    float acc[8][4] = {};
    #pragma unroll
    for (int kc=0; kc<64; kc+=16){
        float4 u0=*(const float4*)(urow+kc), u1=*(const float4*)(urow+kc+4);
        float4 v0=*(const float4*)(vrow+kc), v1=*(const float4*)(vrow+kc+4);
        float4 w4=*(const float4*)(wrow+kc);
        As[lc+0][lr]=lrelu_f(u0.x+v0.x); As[lc+1][lr]=lrelu_f(u0.y+v0.y);
        As[lc+2][lr]=lrelu_f(u0.z+v0.z); As[lc+3][lr]=lrelu_f(u0.w+v0.w);
        As[lc+4][lr]=lrelu_f(u1.x+v1.x); As[lc+5][lr]=lrelu_f(u1.y+v1.y);
        As[lc+6][lr]=lrelu_f(u1.z+v1.z); As[lc+7][lr]=lrelu_f(u1.w+v1.w);
        Bs[lcB+0][lrB]=w4.x; Bs[lcB+1][lrB]=w4.y; Bs[lcB+2][lrB]=w4.z; Bs[lcB+3][lrB]=w4.w;
        __syncthreads();
        #pragma unroll
        for (int kk=0; kk<16; kk++){
            float4 x0 = *(const float4*)&As[kk][ty<<3];
            float4 x1 = *(const float4*)&As[kk][(ty<<3)+4];
            float4 y0 = *(const float4*)&Bs[kk][tx<<2];
            float ar[8]={x0.x,x0.y,x0.z,x0.w,x1.x,x1.y,x1.z,x1.w};
            float br[4]={y0.x,y0.y,y0.z,y0.w};
            #pragma unroll
            for (int i=0;i<8;i++)
                #pragma unroll
                for (int j=0;j<4;j++) acc[i][j] = fmaf(ar[i], br[j], acc[i][j]);
        }
        __syncthreads();
    }
    const int e0 = m0 + (ty<<3);
    const int p0 = e0 / KN;
    const int p7 = (e0+7) / KN;
    const int s  = (p7 != p0) ? (p7*KN - e0) : 8;
    #pragma unroll
    for (int j=0;j<4;j++){
        int c = (tx<<2)+j;
        float bb = bias[c];
        float mA = -3.4e38f, mB = -3.4e38f;
        #pragma unroll
        for (int i=0;i<8;i++){
            float v = lrelu_f(acc[i][j]+bb);
            if (i < s) mA = fmaxf(mA, v); else mB = fmaxf(mB, v);
        }
        atomicMax(&Xout[(size_t)p0*ldx + c], fenc(mA));
        if (p7 != p0) atomicMax(&Xout[(size_t)p7*ldx + c], fenc(mB));
    }
}

// ------------------- exact top-40 radix select: geometry variant (smem keys) -------------
// 3 radix passes (bits 31..8); 24-bit-equal survivors resolved by smallest index.
__global__ void __launch_bounds__(256) topk40_geo(int* __restrict__ OUT)
{
    __shared__ unsigned keys[NP];
    __shared__ int hist[256];
    __shared__ unsigned short cbuf[2][NP];
    __shared__ int warptot[8];
    __shared__ int s_dsel, s_r, s_cout, s_cnc;
    const int row = blockIdx.x, tid = threadIdx.x;
    const int lane = tid & 31, wrp = tid >> 5;
    const int base = (row >> 12) << 12;
    hist[tid] = 0;
    if (tid == 0){ s_r = KN; s_cout = 0; s_cnc = 0; }
    __syncthreads();
    {
        const float4 q0 = g_p4[row];
        const float x0=q0.x, x1=q0.y, x2=q0.z, sn=q0.w;
        for (int i = tid; i < NP; i += 256){
            float4 q = g_p4[base+i];
            float d = 2.f*(x0*q.x + x1*q.y + x2*q.z) - sn - q.w;
            unsigned kx = fenc(d);
            keys[i] = kx;
            int dig = kx >> 24;
            unsigned mm = __match_any_sync(FULLM, dig);
            if ((__ffs(mm)-1) == lane) atomicAdd(&hist[dig], __popc(mm));
        }
    }
    __syncthreads();
    int n_cur = NP, cur = 0;
    for (int pass = 3; pass >= 1; pass--){
        const int sh = pass << 3;
        {
            int val = hist[tid];
            int r_cur = s_r;
            int s = val;
            #pragma unroll
            for (int d=1; d<32; d<<=1){
                int t = __shfl_down_sync(FULLM, s, d);
                if (lane + d < 32) s += t;
            }
            if (lane == 0) warptot[wrp] = s;
            __syncthreads();
            int offs = 0;
            #pragma unroll
            for (int w=0; w<8; w++) if (w > wrp) offs += warptot[w];
            int S = s + offs;
            if (S >= r_cur && S - val < r_cur){ s_dsel = tid; s_r = r_cur - (S - val); }
            __syncthreads();
        }
        const int dsel = s_dsel;
        hist[tid] = 0;
        if (tid == 0) s_cnc = 0;
        __syncthreads();
        const int nt = (n_cur + 255) >> 8;
        for (int it = 0; it < nt; it++){
            int ii = it*256 + tid;
            bool vld = ii < n_cur;
            int gi = 0; unsigned kx = 0;
            if (vld){
                gi = (pass==3) ? ii : (int)cbuf[cur][ii];
                kx = keys[gi];
            }
            int dig = vld ? (int)((kx >> sh) & 255) : 0x1FF;
            bool gt = vld && dig > dsel;
            bool eq = vld && dig == dsel;
            unsigned bg = __ballot_sync(FULLM, gt);
            unsigned be = __ballot_sync(FULLM, eq);
            int baseg = 0, basee = 0;
            if (lane == 0){
                if (bg) baseg = atomicAdd(&s_cout, __popc(bg));
                if (be) basee = atomicAdd(&s_cnc, __popc(be));
            }
            baseg = __shfl_sync(FULLM, baseg, 0);
            basee = __shfl_sync(FULLM, basee, 0);
            unsigned ltm = (1u << lane) - 1u;
            if (gt) OUT[row*KN + baseg + __popc(bg & ltm)] = base + gi;
            if (eq) cbuf[cur^1][basee + __popc(be & ltm)] = (unsigned short)gi;
        }
        __syncthreads();
        n_cur = s_cnc;
        cur ^= 1;
        if (pass > 1){
            const int sh2 = sh - 8;
            const int nt2 = (n_cur + 255) >> 8;
            for (int it = 0; it < nt2; it++){
                int ii = it*256 + tid;
                bool vld = ii < n_cur;
                int dig = 0x1FF;
                if (vld) dig = (keys[cbuf[cur][ii]] >> sh2) & 255;
                unsigned mm = __match_any_sync(FULLM, dig);
                if (vld && (__ffs(mm)-1) == lane) atomicAdd(&hist[dig], __popc(mm));
            }
            __syncthreads();
        }
    }
    // survivors share bits 31..8: take smallest local indices
    if (tid == 0){
        int need = s_r, cw = s_cout;
        int cnt = n_cur;
        for (int s = 0; s < need; s++){
            int bi=-1, bv=1<<30;
            for (int q=0; q<cnt; q++){ int v = cbuf[cur][q]; if (v < bv){ bv=v; bi=q; } }
            OUT[row*KN + cw + s] = base + bv;
            if (bi >= 0) cbuf[cur][bi] = 0xFFFF;
        }
    }
}

// ------------------- exact top-40 radix select: DK variant (keys stay in L2) -------------
__global__ void __launch_bounds__(256) topk40_dk(
    const unsigned* __restrict__ DK, int* __restrict__ OUT)
{
    __shared__ int hist[256];
    __shared__ unsigned short cbuf[2][NP];
    __shared__ int warptot[8];
    __shared__ int s_dsel, s_r, s_cout, s_cnc;
    const int row = blockIdx.x, tid = threadIdx.x;
    const int lane = tid & 31, wrp = tid >> 5;
    const int base = (row >> 12) << 12;
    const unsigned* drow = DK + (size_t)row*NP;
    hist[tid] = 0;
    if (tid == 0){ s_r = KN; s_cout = 0; s_cnc = 0; }
    __syncthreads();
    {
        const uint4* d4 = (const uint4*)drow;
        for (int i = tid; i < NP/4; i += 256){
            uint4 k4 = __ldg(&d4[i]);
            unsigned ks[4] = {k4.x, k4.y, k4.z, k4.w};
            #pragma unroll
            for (int j=0;j<4;j++){
                int dig = ks[j] >> 24;
                unsigned mm = __match_any_sync(FULLM, dig);
                if ((__ffs(mm)-1) == lane) atomicAdd(&hist[dig], __popc(mm));
            }
        }
    }
    __syncthreads();
    int n_cur = NP, cur = 0;
    for (int pass = 3; pass >= 1; pass--){
        const int sh = pass << 3;
        {
            int val = hist[tid];
            int r_cur = s_r;
            int s = val;
            #pragma unroll
            for (int d=1; d<32; d<<=1){
                int t = __shfl_down_sync(FULLM, s, d);
                if (lane + d < 32) s += t;
            }
            if (lane == 0) warptot[wrp] = s;
            __syncthreads();
            int offs = 0;
            #pragma unroll
            for (int w=0; w<8; w++) if (w > wrp) offs += warptot[w];
            int S = s + offs;
            if (S >= r_cur && S - val < r_cur){ s_dsel = tid; s_r = r_cur - (S - val); }
            __syncthreads();
        }
        const int dsel = s_dsel;
        hist[tid] = 0;
        if (tid == 0) s_cnc = 0;
        __syncthreads();
        const int nt = (n_cur + 255) >> 8;
        for (int it = 0; it < nt; it++){
            int ii = it*256 + tid;
            bool vld = ii < n_cur;
            int gi = 0; unsigned kx = 0;
            if (vld){
                gi = (pass==3) ? ii : (int)cbuf[cur][ii];
                kx = __ldg(&drow[gi]);
            }
            int dig = vld ? (int)((kx >> sh) & 255) : 0x1FF;
            bool gt = vld && dig > dsel;
            bool eq = vld && dig == dsel;
            unsigned bg = __ballot_sync(FULLM, gt);
            unsigned be = __ballot_sync(FULLM, eq);
            int baseg = 0, basee = 0;
            if (lane == 0){
                if (bg) baseg = atomicAdd(&s_cout, __popc(bg));
                if (be) basee = atomicAdd(&s_cnc, __popc(be));
            }
            baseg = __shfl_sync(FULLM, baseg, 0);
            basee = __shfl_sync(FULLM, basee, 0);
            unsigned ltm = (1u << lane) - 1u;
            if (gt) OUT[row*KN + baseg + __popc(bg & ltm)] = base + gi;
            if (eq) cbuf[cur^1][basee + __popc(be & ltm)] = (unsigned short)gi;
        }
        __syncthreads();
        n_cur = s_cnc;
        cur ^= 1;
        if (pass > 1){
            const int sh2 = sh - 8;
            const int nt2 = (n_cur + 255) >> 8;
            for (int it = 0; it < nt2; it++){
                int ii = it*256 + tid;
                bool vld = ii < n_cur;
                int dig = 0x1FF;
                if (vld) dig = (__ldg(&drow[cbuf[cur][ii]]) >> sh2) & 255;
                unsigned mm = __match_any_sync(FULLM, dig);
                if (vld && (__ffs(mm)-1) == lane) atomicAdd(&hist[dig], __popc(mm));
            }
            __syncthreads();
        }
    }
    if (tid == 0){
        int need = s_r, cw = s_cout;
        int cnt = n_cur;
        for (int s = 0; s < need; s++){
            int bi=-1, bv=1<<30;
            for (int q=0; q<cnt; q++){ int v = cbuf[cur][q]; if (v < bv){ bv=v; bi=q; } }
            OUT[row*KN + cw + s] = base + bv;
            if (bi >= 0) cbuf[cur][bi] = 0xFFFF;
        }
    }
}

// ----------------------------- small kernels ---------------------------------------------
__global__ void sqnormk(const float* __restrict__ X, int ld, int C, float4* __restrict__ p4){
    int p = blockIdx.x*256 + threadIdx.x;
    if (p>=TP) return;
    const float* r = X + (size_t)p*ld;
    float s=0.f;
    for (int c=0;c<C;c++) s = fmaf(r[c],r[c],s);
    g_sq[p]=s;
    if (p4) p4[p] = make_float4(r[0], r[1], r[2], s);
}
__global__ void uv1k(const float* __restrict__ P, const float* __restrict__ W1, const float* __restrict__ b1){
    int g = blockIdx.x*256 + threadIdx.x;
    int o = g&63, p = g>>6;
    const float* x = P + (size_t)p*3;
    float u=0.f, v=b1[o];
    #pragma unroll
    for (int c=0;c<3;c++){
        float wa=W1[o*6+c], wb=W1[o*6+3+c];
        u = fmaf(wa, x[c], u);
        v = fmaf(wb-wa, x[c], v);
    }
    g_uv[(size_t)p*128 + o]      = u;
    g_uv[(size_t)p*128 + 64 + o] = v;
}
__global__ void wprep2k(const float* __restrict__ W, const float* __restrict__ b,
                        float* __restrict__ wad, float* __restrict__ bv){
    int g = blockIdx.x*256 + threadIdx.x;
    if (g < 8192){
        int o = g>>6, c = g&63;
        float val;
        if (o < 64) val = W[o*128 + c];
        else        val = W[(o-64)*128 + 64 + c] - W[(o-64)*128 + c];
        wad[g] = val;
    }
    if (g < 128) bv[g] = (g < 64) ? 0.f : b[g-64];
}
__global__ void initenck(int off){
    int g = blockIdx.x*256 + threadIdx.x;
    int p=g>>6, c=g&63;
    ((unsigned*)g_xc)[(size_t)p*192 + off + c]=0u;
}
__global__ void decenck(int off){
    int g = blockIdx.x*256 + threadIdx.x;
    int p=g>>6, c=g&63;
    size_t ix=(size_t)p*192 + off + c;
    unsigned e = ((unsigned*)g_xc)[ix];
    g_xc[ix]=fdec(e);
}
__global__ void initgk(){ int g=blockIdx.x*256+threadIdx.x; if (g<NB*1024) g_gm[g]=0u; }
__global__ void maxedgek(){
    int p = blockIdx.x, o = threadIdx.x;
    float v = g_uv[(size_t)p*128 + 64 + o];
    float best = -3.4e38f;
    #pragma unroll 4
    for (int j=0;j<KN;j++){
        int jg = g_idx[p*KN+j];
        best = fmaxf(best, lrelu_f(g_uv[(size_t)jg*128 + o] + v));
    }
    g_xc[(size_t)p*192 + 128 + o] = best;
}
__global__ void wp1tk(const float* __restrict__ Wp1){
    int g = blockIdx.x*256 + threadIdx.x;
    if (g >= 1088*256) return;
    int o = g&255, j = g>>8;
    g_wt[(size_t)j*256 + o] = Wp1[(size_t)o*1280 + 192 + j];
}
__global__ void __launch_bounds__(256) globk(
    const float* __restrict__ label, const float* __restrict__ W7,
    const float* __restrict__ b7, const float* __restrict__ bp1)
{
    __shared__ float gl[1088];
    int b = blockIdx.x, tid = threadIdx.x;
    for (int i=tid;i<1024;i+=256) gl[i]=fdec(g_gm[b*1024+i]);
    if (tid<64){
        float a=b7[tid];
        #pragma unroll
        for (int c=0;c<16;c++) a = fmaf(label[b*16+c], W7[tid*16+c], a);
        gl[1024+tid]=lrelu_f(a);
    }
    __syncthreads();
    float a = bp1[tid];
    #pragma unroll 8
    for (int j=0;j<1088;j++) a = fmaf(g_wt[(size_t)j*256 + tid], gl[j], a);
    g_c1[b*256+tid]=a;
}
__global__ void outk(const float* __restrict__ Wp4, float* __restrict__ out){
    int g = blockIdx.x*256 + threadIdx.x;
    int s = g%6, p = g/6;
    const float* h = g_h3 + (size_t)p*128;
    const float* w = Wp4 + s*128;
    float a=0.f;
    #pragma unroll 8
    for (int c=0;c<128;c++) a = fmaf(h[c], w[c], a);
    out[g]=a;
}

// ----------------------------- host ------------------------------------------------------
static void* symaddr(const void* s){ void* p=nullptr; cudaGetSymbolAddress(&p, s); return p; }

extern "C" void kernel_launch(void* const* d_in, const int* in_sizes, int n_in,
                              void* d_out, int out_size)
{
    const float* points=(const float*)d_in[0];
    const float* label =(const float*)d_in[1];
    const float *W1=(const float*)d_in[2],  *b1=(const float*)d_in[3];
    const float *W2=(const float*)d_in[4],  *b2=(const float*)d_in[5];
    const float *W3=(const float*)d_in[6],  *b3=(const float*)d_in[7];
    const float *W4=(const float*)d_in[8],  *b4=(const float*)d_in[9];
    const float *W5=(const float*)d_in[10], *b5=(const float*)d_in[11];
    const float *W6=(const float*)d_in[12], *b6=(const float*)d_in[13];
    const float *W7=(const float*)d_in[14], *b7=(const float*)d_in[15];
    const float *Wp1=(const float*)d_in[16],*bp1=(const float*)d_in[17];
    const float *Wp2=(const float*)d_in[18],*bp2=(const float*)d_in[19];
    const float *Wp3=(const float*)d_in[20],*bp3=(const float*)d_in[21];
    const float *Wp4=(const float*)d_in[22];
    float* out=(float*)d_out;

    unsigned* pDK =(unsigned*)symaddr(g_DK);
    int*      pIdx=(int*)     symaddr(g_idx);
    float*    pUV =(float*)   symaddr(g_uv);
    float*    pXc =(float*)   symaddr(g_xc);
    float4*   pP4 =(float4*)  symaddr(g_p4);
    unsigned* pGm =(unsigned*)symaddr(g_gm);
    float*    pC1 =(float*)   symaddr(g_c1);
    float*    pH1 =(float*)   symaddr(g_h1);
    float*    pH2 =(float*)   symaddr(g_h2);
    float*    pH3 =(float*)   symaddr(g_h3);
    float*    pWad3=(float*)  symaddr(g_wad3);
    float*    pBv3 =(float*)  symaddr(g_bv3);
    float*    pWad5=(float*)  symaddr(g_wad5);
    float*    pBv5 =(float*)  symaddr(g_bv5);

    // launches 1-3 prep; launch 4 = topk40_geo for ncu
    sqnormk<<<64,256>>>(points,3,3,pP4);
    wprep2k<<<32,256>>>(W3,b3,pWad3,pBv3);
    wprep2k<<<32,256>>>(W5,b5,pWad5,pBv5);
    topk40_geo<<<TP,256>>>(pIdx);
    wp1tk<<<1088,256>>>(Wp1);
    initgk<<<16,256>>>();

    // ---------- EdgeConv block 1 ----------
    uv1k<<<4096,256>>>(points,W1,b1);
    initenck<<<4096,256>>>(0);
    edge_gemm<<<NE/128,256>>>(pUV,pIdx,W2,b2,(unsigned*)pXc+0,192);
    decenck<<<4096,256>>>(0);

    // ---------- EdgeConv block 2 ----------
    sqnormk<<<64,256>>>(pXc+0,192,64,nullptr);
    dist_gemm_sym<<<dim3(528,1,NB),256>>>(pXc+0,192,pDK);
    topk40_dk<<<TP,256>>>(pDK, pIdx);
    gemm_big<1><<<dim3(1,128),256>>>(pXc+0,192, pWad3,64, pUV,128, 64, pBv3,nullptr,0);
    initenck<<<4096,256>>>(64);
    edge_gemm<<<NE/128,256>>>(pUV,pIdx,W4,b4,(unsigned*)pXc+64,192);
    decenck<<<4096,256>>>(64);

    // ---------- EdgeConv block 3 (single layer -> gather/max) ----------
    sqnormk<<<64,256>>>(pXc+64,192,64,nullptr);
    dist_gemm_sym<<<dim3(528,1,NB),256>>>(pXc+64,192,pDK);
    topk40_dk<<<TP,256>>>(pDK, pIdx);
    gemm_big<1><<<dim3(1,128),256>>>(pXc+64,192, pWad5,64, pUV,128, 64, pBv5,nullptr,0);
    maxedgek<<<TP,64>>>();

    // ---------- global feature ----------
    gemm_big<5><<<dim3(8,128),256>>>(pXc,192, W6,192, nullptr,0, 192, b6,pGm,1024);
    globk<<<NB,256>>>(label,W7,b7,bp1);

    // ---------- segmentation head ----------
    gemm_big<3><<<dim3(2,128),256>>>(pXc,192, Wp1,1280, pH1,256, 192, pC1,nullptr,256);
    gemm_big<2><<<dim3(2,128),256>>>(pH1,256, Wp2,256,  pH2,256, 256, bp2,nullptr,0);
    gemm_big<2><<<dim3(1,128),256>>>(pH2,256, Wp3,256,  pH3,128, 256, bp3,nullptr,0);
    outk<<<384,256>>>(Wp4,out);
}